// round 12
// baseline (speedup 1.0000x reference)
#include <cuda_runtime.h>
#include <cuda_bf16.h>
#include <cstdint>

// Problem constants
#define NN 50000
#define EE 400000
#define INDIM 256
#define HDIM 128
#define ALPHA_C 0.2f
#define INV_TEMP (1.0f / 0.55f)
#define ASTRIDE 72            // bf16 elems per smem row (144B: conflict-free ldmatrix)

// Scratch (device globals)
__device__ float g_Wh[NN * HDIM];
__device__ float g_U[NN * HDIM];
__device__ float g_V[NN * HDIM];
__device__ int   g_rowptr[NN + 1];
// B fragments in native mma register layout (bf16x2 words):
// g_WB : [leg2][kt16][nt16][lane32][reg2]   (W  -> 128KB)
__device__ uint32_t g_WB[32768];
// g_WaB: [leg2][q4][kt4][nt8][lane32][reg2] (Wa -> 64KB)
__device__ uint32_t g_WaB[16384];

// ---------------- helpers ----------------
__device__ __forceinline__ uint32_t su32(const void* p) {
    uint32_t a;
    asm("{ .reg .u64 t; cvta.to.shared.u64 t, %1; cvt.u32.u64 %0, t; }" : "=r"(a) : "l"(p));
    return a;
}
__device__ __forceinline__ void split2(float v, unsigned short& hi, unsigned short& lo) {
    __nv_bfloat16 b = __float2bfloat16_rn(v);
    hi = __bfloat16_as_ushort(b);
    lo = __bfloat16_as_ushort(__float2bfloat16_rn(v - __bfloat162float(b)));
}
__device__ __forceinline__ void mma_bf16(float* c, const uint32_t* a, uint32_t b0, uint32_t b1) {
    asm volatile(
        "mma.sync.aligned.m16n8k16.row.col.f32.bf16.bf16.f32 "
        "{%0,%1,%2,%3},{%4,%5,%6,%7},{%8,%9},{%0,%1,%2,%3};"
        : "+f"(c[0]), "+f"(c[1]), "+f"(c[2]), "+f"(c[3])
        : "r"(a[0]), "r"(a[1]), "r"(a[2]), "r"(a[3]), "r"(b0), "r"(b1));
}
__device__ __forceinline__ void ldmA(uint32_t* a, uint32_t addr) {
    asm volatile("ldmatrix.sync.aligned.m8n8.x4.shared.b16 {%0,%1,%2,%3}, [%4];"
        : "=r"(a[0]), "=r"(a[1]), "=r"(a[2]), "=r"(a[3]) : "r"(addr));
}

// ---------------------------------------------------------------------------
// K0: CSR row pointers from sorted dst.
// ---------------------------------------------------------------------------
__global__ void k_rowptr(const int* __restrict__ dst, int E, int N) {
    int e = blockIdx.x * blockDim.x + threadIdx.x;
    if (e > E) return;
    int cur  = (e < E) ? dst[e] : N;
    int prev = (e == 0) ? -1 : dst[e - 1];
    for (int n = prev + 1; n <= cur; n++) g_rowptr[n] = e;
}

// ---------------------------------------------------------------------------
// Prep W -> B fragments. idx = [kt16][nt16][lane32][reg2].
// ---------------------------------------------------------------------------
__global__ void k_prep_w(const float* __restrict__ W) {
    int idx = blockIdx.x * 256 + threadIdx.x;    // 0..16383
    int reg = idx & 1, lane = (idx >> 1) & 31, nt = (idx >> 6) & 15, kt = idx >> 10;
    int cc = lane & 3, g = lane >> 2;
    int k0 = kt * 16 + reg * 8 + cc * 2;
    int n  = nt * 8 + g;
    unsigned short h0, l0, h1, l1;
    split2(W[(size_t)k0 * HDIM + n], h0, l0);
    split2(W[(size_t)(k0 + 1) * HDIM + n], h1, l1);
    g_WB[idx]         = ((uint32_t)h1 << 16) | h0;
    g_WB[16384 + idx] = ((uint32_t)l1 << 16) | l0;
}

// ---------------------------------------------------------------------------
// Prep Wa -> B fragments. idx = [q4][kt4][nt8][lane32][reg2].
// ---------------------------------------------------------------------------
__global__ void k_prep_wa(const float* __restrict__ Wa) {
    int idx = blockIdx.x * 256 + threadIdx.x;    // 0..8191
    int reg = idx & 1, lane = (idx >> 1) & 31, nt = (idx >> 6) & 7;
    int kt = (idx >> 9) & 3, q = idx >> 11;
    int cc = lane & 3, g = lane >> 2;
    int h = q & 1, p = q >> 1;
    int f0 = kt * 16 + reg * 8 + cc * 2;
    int n  = nt * 8 + g;
    unsigned short h0, l0, h1, l1;
    split2(Wa[h * 8192 + (p * 64 + f0) * 64 + n], h0, l0);
    split2(Wa[h * 8192 + (p * 64 + f0 + 1) * 64 + n], h1, l1);
    g_WaB[idx]        = ((uint32_t)h1 << 16) | h0;
    g_WaB[8192 + idx] = ((uint32_t)l1 << 16) | l0;
}

// ---------------------------------------------------------------------------
// K1+K2 fused, register-dieted for 3 CTAs/SM:
//  Phase 1: Wh = x @ W (direct staging, no reg prefetch — occupancy hides DRAM)
//  Phase 2: split in-register Wh acc -> smem A[h][leg]; fp32 Wh -> gmem
//  Phase 3: U/V = Wh_h @ Wa, mt-OUTERMOST so only uacc[4][4] (16 regs) live.
// ---------------------------------------------------------------------------
__global__ __launch_bounds__(256, 3) void k_whuv_mma(const float* __restrict__ x, int N) {
    __shared__ __align__(16) __nv_bfloat16 A[2][2][64 * ASTRIDE];  // [h][leg]
    int tid = threadIdx.x, wid = tid >> 5, lane = tid & 31;
    int bm = blockIdx.x * 64;
    int wm = wid & 1, wn = wid >> 1;          // phase-1 roles: 2m x 4n
    uint32_t ah_b = su32(A[0][0]), al_b = su32(A[0][1]);

    // ---------------- Phase 1: Wh ----------------
    float acc[2][4][4];
#pragma unroll
    for (int mt = 0; mt < 2; mt++)
#pragma unroll
        for (int nt = 0; nt < 4; nt++)
#pragma unroll
            for (int r = 0; r < 4; r++) acc[mt][nt][r] = 0.f;

    int lrow = lane & 15, lch = (lane >> 4) * 8;

    for (int kc = 0; kc < 4; kc++) {
        // stage A chunk: 64 rows x 64 k, split hi/lo (1024 float4, 4/thread)
#pragma unroll
        for (int i = 0; i < 4; i++) {
            int c = tid + i * 256;
            int row = c >> 4, kq = (c & 15) * 4;
            int gr = bm + row;
            float4 v = make_float4(0.f, 0.f, 0.f, 0.f);
            if (gr < N) v = *(const float4*)(x + (size_t)gr * INDIM + kc * 64 + kq);
            unsigned short hx, lx, hy, ly, hz, lz, hw, lw;
            split2(v.x, hx, lx); split2(v.y, hy, ly);
            split2(v.z, hz, lz); split2(v.w, hw, lw);
            *(uint2*)&A[0][0][row * ASTRIDE + kq] =
                make_uint2(((uint32_t)hy << 16) | hx, ((uint32_t)hw << 16) | hz);
            *(uint2*)&A[0][1][row * ASTRIDE + kq] =
                make_uint2(((uint32_t)ly << 16) | lx, ((uint32_t)lw << 16) | lz);
        }
        __syncthreads();

#pragma unroll
        for (int kk = 0; kk < 4; kk++) {
            uint32_t afh[2][4], afl[2][4];
#pragma unroll
            for (int mt = 0; mt < 2; mt++) {
                uint32_t off = ((wm * 32 + mt * 16 + lrow) * ASTRIDE + kk * 16 + lch) * 2;
                ldmA(afh[mt], ah_b + off);
                ldmA(afl[mt], al_b + off);
            }
            int kt = kc * 4 + kk;
            const uint32_t* Bp = g_WB + (size_t)(kt * 16 + wn * 4) * 64 + lane * 2;
#pragma unroll
            for (int nt = 0; nt < 4; nt++) {
                uint2 bh = *(const uint2*)(Bp + nt * 64);
                uint2 bl = *(const uint2*)(Bp + nt * 64 + 16384);
#pragma unroll
                for (int mt = 0; mt < 2; mt++) {
                    mma_bf16(acc[mt][nt], afh[mt], bh.x, bh.y);
                    mma_bf16(acc[mt][nt], afh[mt], bl.x, bl.y);
                    mma_bf16(acc[mt][nt], afl[mt], bh.x, bh.y);
                }
            }
        }
        __syncthreads();
    }

    // ---------------- Phase 2: epilogue + re-stage Wh (split) ----------------
    {
        int g = lane >> 2, cc = lane & 3;
#pragma unroll
        for (int mt = 0; mt < 2; mt++)
#pragma unroll
            for (int nt = 0; nt < 4; nt++) {
                int lrow0 = wm * 32 + mt * 16 + g;       // local tile row
                int col = wn * 32 + nt * 8 + cc * 2;
                int h = col >> 6, kl = col & 63;
                unsigned short h0, l0, h1, l1, h2, l2, h3, l3;
                split2(acc[mt][nt][0], h0, l0);
                split2(acc[mt][nt][1], h1, l1);
                split2(acc[mt][nt][2], h2, l2);
                split2(acc[mt][nt][3], h3, l3);
                *(uint32_t*)&A[h][0][lrow0 * ASTRIDE + kl] = ((uint32_t)h1 << 16) | h0;
                *(uint32_t*)&A[h][1][lrow0 * ASTRIDE + kl] = ((uint32_t)l1 << 16) | l0;
                *(uint32_t*)&A[h][0][(lrow0 + 8) * ASTRIDE + kl] = ((uint32_t)h3 << 16) | h2;
                *(uint32_t*)&A[h][1][(lrow0 + 8) * ASTRIDE + kl] = ((uint32_t)l3 << 16) | l2;
                int grow0 = bm + lrow0;
                if (grow0 < N)
                    *(float2*)(g_Wh + (size_t)grow0 * HDIM + col) =
                        make_float2(acc[mt][nt][0], acc[mt][nt][1]);
                if (grow0 + 8 < N)
                    *(float2*)(g_Wh + (size_t)(grow0 + 8) * HDIM + col) =
                        make_float2(acc[mt][nt][2], acc[mt][nt][3]);
            }
    }
    __syncthreads();

    // ---------------- Phase 3: U/V (mt-outermost, small live set) ----------------
    {
        int q = wid >> 1, nh = wid & 1, h = q & 1;
        uint32_t uah_b = su32(A[h][0]), ual_b = su32(A[h][1]);
        float* base = (q >> 1) ? g_V : g_U;
        int g = lane >> 2, cc = lane & 3;

#pragma unroll 1
        for (int mt = 0; mt < 4; mt++) {
            float uacc[4][4];
#pragma unroll
            for (int nt = 0; nt < 4; nt++)
#pragma unroll
                for (int r = 0; r < 4; r++) uacc[nt][r] = 0.f;

#pragma unroll
            for (int kk = 0; kk < 4; kk++) {
                uint32_t afh[4], afl[4];
                uint32_t off = ((mt * 16 + lrow) * ASTRIDE + kk * 16 + lch) * 2;
                ldmA(afh, uah_b + off);
                ldmA(afl, ual_b + off);
                const uint32_t* Bp = g_WaB + (size_t)((q * 4 + kk) * 8 + nh * 4) * 64 + lane * 2;
#pragma unroll
                for (int nt = 0; nt < 4; nt++) {
                    uint2 bh = *(const uint2*)(Bp + nt * 64);
                    uint2 bl = *(const uint2*)(Bp + nt * 64 + 8192);
                    mma_bf16(uacc[nt], afh, bh.x, bh.y);
                    mma_bf16(uacc[nt], afh, bl.x, bl.y);
                    mma_bf16(uacc[nt], afl, bh.x, bh.y);
                }
            }

            int row0 = bm + mt * 16 + g;
#pragma unroll
            for (int nt = 0; nt < 4; nt++) {
                int col = h * 64 + nh * 32 + nt * 8 + cc * 2;
                if (row0 < N)
                    *(float2*)(base + (size_t)row0 * HDIM + col) =
                        make_float2(uacc[nt][0], uacc[nt][1]);
                if (row0 + 8 < N)
                    *(float2*)(base + (size_t)(row0 + 8) * HDIM + col) =
                        make_float2(uacc[nt][2], uacc[nt][3]);
            }
        }
    }
}

// ---------------------------------------------------------------------------
// K3: fused edge kernel — single-pass online softmax + aggregation,
// 2 edges per iteration. One warp per dst node. (unchanged)
// ---------------------------------------------------------------------------
__global__ __launch_bounds__(256) void k_edge_fused(const float* __restrict__ avec,
                                                    const int* __restrict__ src,
                                                    float* __restrict__ out, int N) {
    int t = blockIdx.x * blockDim.x + threadIdx.x;
    int n = t >> 5, lane = t & 31;
    if (n >= N) return;
    int e0 = g_rowptr[n], e1 = g_rowptr[n + 1];
    const float4* U4  = (const float4*)g_U;
    const float4* V4  = (const float4*)g_V;
    const float4* Wh4 = (const float4*)g_Wh;
    float4 a = ((const float4*)avec)[lane];
    float4 acc = make_float4(0.f, 0.f, 0.f, 0.f);
    float ssum = 0.f;

    if (e1 > e0) {
        float4 v = V4[(size_t)n * 32 + lane];
        float m = -1e30f;

        float4 u0 = make_float4(0.f, 0.f, 0.f, 0.f), w0 = u0, u1 = u0, w1 = u0;
        {
            int s0 = src[e0];
            u0 = U4[(size_t)s0 * 32 + lane];
            w0 = Wh4[(size_t)s0 * 32 + lane];
            if (e0 + 1 < e1) {
                int s1 = src[e0 + 1];
                u1 = U4[(size_t)s1 * 32 + lane];
                w1 = Wh4[(size_t)s1 * 32 + lane];
            }
        }

        for (int e = e0; e < e1; e += 2) {
            bool two = (e + 1 < e1);
            float4 cu0 = u0, cw0 = w0, cu1 = u1, cw1 = w1;
            if (e + 2 < e1) {
                int s0 = src[e + 2];
                u0 = U4[(size_t)s0 * 32 + lane];
                w0 = Wh4[(size_t)s0 * 32 + lane];
            }
            if (e + 3 < e1) {
                int s1 = src[e + 3];
                u1 = U4[(size_t)s1 * 32 + lane];
                w1 = Wh4[(size_t)s1 * 32 + lane];
            }
            float q, z0, z1;
            q = cu0.x + v.x; z0  = fmaxf(q, ALPHA_C * q) * a.x;
            q = cu1.x + v.x; z1  = fmaxf(q, ALPHA_C * q) * a.x;
            q = cu0.y + v.y; z0 += fmaxf(q, ALPHA_C * q) * a.y;
            q = cu1.y + v.y; z1 += fmaxf(q, ALPHA_C * q) * a.y;
            q = cu0.z + v.z; z0 += fmaxf(q, ALPHA_C * q) * a.z;
            q = cu1.z + v.z; z1 += fmaxf(q, ALPHA_C * q) * a.z;
            q = cu0.w + v.w; z0 += fmaxf(q, ALPHA_C * q) * a.w;
            q = cu1.w + v.w; z1 += fmaxf(q, ALPHA_C * q) * a.w;
            z0 += __shfl_xor_sync(0xffffffffu, z0, 8);
            z1 += __shfl_xor_sync(0xffffffffu, z1, 8);
            z0 += __shfl_xor_sync(0xffffffffu, z0, 4);
            z1 += __shfl_xor_sync(0xffffffffu, z1, 4);
            z0 += __shfl_xor_sync(0xffffffffu, z0, 2);
            z1 += __shfl_xor_sync(0xffffffffu, z1, 2);
            z0 += __shfl_xor_sync(0xffffffffu, z0, 1);
            z1 += __shfl_xor_sync(0xffffffffu, z1, 1);
            float l0 = z0 * INV_TEMP;
            float l1 = two ? (z1 * INV_TEMP) : -1e30f;
            float mn = fmaxf(m, fmaxf(l0, l1));
            float cs = __expf(m - mn);
            float p0 = __expf(l0 - mn);
            float p1 = __expf(l1 - mn);
            ssum = ssum * cs + p0 + p1;
            acc.x = acc.x * cs + p0 * cw0.x + p1 * cw1.x;
            acc.y = acc.y * cs + p0 * cw0.y + p1 * cw1.y;
            acc.z = acc.z * cs + p0 * cw0.z + p1 * cw1.z;
            acc.w = acc.w * cs + p0 * cw0.w + p1 * cw1.w;
            m = mn;
        }
        float inv = 1.0f / (ssum + 1e-9f);
        acc.x *= inv; acc.y *= inv; acc.z *= inv; acc.w *= inv;
    }

    float bx = __shfl_down_sync(0xffffffffu, acc.x, 16);
    float by = __shfl_down_sync(0xffffffffu, acc.y, 16);
    float bz = __shfl_down_sync(0xffffffffu, acc.z, 16);
    float bw = __shfl_down_sync(0xffffffffu, acc.w, 16);
    if (lane < 16) {
        float4 r = make_float4((acc.x + bx) * 0.5f, (acc.y + by) * 0.5f,
                               (acc.z + bz) * 0.5f, (acc.w + bw) * 0.5f);
        ((float4*)out)[(size_t)n * 16 + lane] = r;
    }
}

// ---------------------------------------------------------------------------
extern "C" void kernel_launch(void* const* d_in, const int* in_sizes, int n_in,
                              void* d_out, int out_size) {
    const float* x     = (const float*)d_in[0];
    const float* W     = (const float*)d_in[1];
    const float* Wattn = (const float*)d_in[2];
    const float* avec  = (const float*)d_in[3];
    const int*   src   = (const int*)d_in[4];
    const int*   dst   = (const int*)d_in[5];
    float* out = (float*)d_out;
    int N = in_sizes[0] / INDIM;
    int E = in_sizes[4];

    k_rowptr<<<(E + 1 + 255) / 256, 256>>>(dst, E, N);
    k_prep_w<<<64, 256>>>(W);
    k_prep_wa<<<32, 256>>>(Wattn);
    k_whuv_mma<<<(N + 63) / 64, 256>>>(x, N);
    k_edge_fused<<<(N + 7) / 8, 256>>>(avec, src, out, N);
}

// round 13
// speedup vs baseline: 1.0746x; 1.0746x over previous
#include <cuda_runtime.h>
#include <cuda_bf16.h>
#include <cstdint>

// Problem constants
#define NN 50000
#define EE 400000
#define INDIM 256
#define HDIM 128
#define ALPHA_C 0.2f
#define INV_TEMP (1.0f / 0.55f)
#define ASTRIDE 72            // bf16 elems per smem row (144B: conflict-free ldmatrix)

// Scratch (device globals)
__device__ float g_Wh[NN * HDIM];
__device__ float g_U[NN * HDIM];
__device__ float g_V[NN * HDIM];
__device__ int   g_rowptr[NN + 1];
// B fragments in native mma register layout (bf16x2 words):
// g_WB : [leg2][kt16][nt16][lane32][reg2]   (W  -> 128KB)
__device__ uint32_t g_WB[32768];
// g_WaB: [leg2][q4][kt4][nt8][lane32][reg2] (Wa -> 64KB)
__device__ uint32_t g_WaB[16384];

// ---------------- helpers ----------------
__device__ __forceinline__ uint32_t su32(const void* p) {
    uint32_t a;
    asm("{ .reg .u64 t; cvta.to.shared.u64 t, %1; cvt.u32.u64 %0, t; }" : "=r"(a) : "l"(p));
    return a;
}
__device__ __forceinline__ void split2(float v, unsigned short& hi, unsigned short& lo) {
    __nv_bfloat16 b = __float2bfloat16_rn(v);
    hi = __bfloat16_as_ushort(b);
    lo = __bfloat16_as_ushort(__float2bfloat16_rn(v - __bfloat162float(b)));
}
__device__ __forceinline__ void mma_bf16(float* c, const uint32_t* a, uint32_t b0, uint32_t b1) {
    asm volatile(
        "mma.sync.aligned.m16n8k16.row.col.f32.bf16.bf16.f32 "
        "{%0,%1,%2,%3},{%4,%5,%6,%7},{%8,%9},{%0,%1,%2,%3};"
        : "+f"(c[0]), "+f"(c[1]), "+f"(c[2]), "+f"(c[3])
        : "r"(a[0]), "r"(a[1]), "r"(a[2]), "r"(a[3]), "r"(b0), "r"(b1));
}
__device__ __forceinline__ void ldmA(uint32_t* a, uint32_t addr) {
    asm volatile("ldmatrix.sync.aligned.m8n8.x4.shared.b16 {%0,%1,%2,%3}, [%4];"
        : "=r"(a[0]), "=r"(a[1]), "=r"(a[2]), "=r"(a[3]) : "r"(addr));
}

// ---------------------------------------------------------------------------
// K0: CSR row pointers from sorted dst.
// ---------------------------------------------------------------------------
__global__ void k_rowptr(const int* __restrict__ dst, int E, int N) {
    int e = blockIdx.x * blockDim.x + threadIdx.x;
    if (e > E) return;
    int cur  = (e < E) ? dst[e] : N;
    int prev = (e == 0) ? -1 : dst[e - 1];
    for (int n = prev + 1; n <= cur; n++) g_rowptr[n] = e;
}

// ---------------------------------------------------------------------------
// Prep W -> B fragments. idx = [kt16][nt16][lane32][reg2].
// ---------------------------------------------------------------------------
__global__ void k_prep_w(const float* __restrict__ W) {
    int idx = blockIdx.x * 256 + threadIdx.x;    // 0..16383
    int reg = idx & 1, lane = (idx >> 1) & 31, nt = (idx >> 6) & 15, kt = idx >> 10;
    int cc = lane & 3, g = lane >> 2;
    int k0 = kt * 16 + reg * 8 + cc * 2;
    int n  = nt * 8 + g;
    unsigned short h0, l0, h1, l1;
    split2(W[(size_t)k0 * HDIM + n], h0, l0);
    split2(W[(size_t)(k0 + 1) * HDIM + n], h1, l1);
    g_WB[idx]         = ((uint32_t)h1 << 16) | h0;
    g_WB[16384 + idx] = ((uint32_t)l1 << 16) | l0;
}

// ---------------------------------------------------------------------------
// Prep Wa -> B fragments. idx = [q4][kt4][nt8][lane32][reg2].
// ---------------------------------------------------------------------------
__global__ void k_prep_wa(const float* __restrict__ Wa) {
    int idx = blockIdx.x * 256 + threadIdx.x;    // 0..8191
    int reg = idx & 1, lane = (idx >> 1) & 31, nt = (idx >> 6) & 7;
    int kt = (idx >> 9) & 3, q = idx >> 11;
    int cc = lane & 3, g = lane >> 2;
    int h = q & 1, p = q >> 1;
    int f0 = kt * 16 + reg * 8 + cc * 2;
    int n  = nt * 8 + g;
    unsigned short h0, l0, h1, l1;
    split2(Wa[h * 8192 + (p * 64 + f0) * 64 + n], h0, l0);
    split2(Wa[h * 8192 + (p * 64 + f0 + 1) * 64 + n], h1, l1);
    g_WaB[idx]        = ((uint32_t)h1 << 16) | h0;
    g_WaB[8192 + idx] = ((uint32_t)l1 << 16) | l0;
}

// ---------------------------------------------------------------------------
// K1+K2 fused (R11 config + double-buffered phase-1 pipeline):
//  Phase 1: Wh = x @ W. A staged in the TWO buffer pairs A[0][*]/A[1][*]
//    (phase-3 buffers are idle during phase 1 -> free double buffer).
//    Iter k: STS chunk k+1 (regs ready) -> LDG chunk k+2 -> mma chunk k -> sync.
//  Phase 2: split in-register Wh acc -> smem A[h][leg]; fp32 Wh -> gmem.
//  Phase 3: U/V = Wh_h @ Wa (wide R11 version).
// ---------------------------------------------------------------------------
__global__ __launch_bounds__(256, 2) void k_whuv_mma(const float* __restrict__ x, int N) {
    __shared__ __align__(16) __nv_bfloat16 A[2][2][64 * ASTRIDE];  // [buf/h][leg]
    int tid = threadIdx.x, wid = tid >> 5, lane = tid & 31;
    int bm = blockIdx.x * 64;
    int wm = wid & 1, wn = wid >> 1;          // phase-1 roles: 2m x 4n
    int lrow = lane & 15, lch = (lane >> 4) * 8;
    int srow = tid >> 4, skq = (tid & 15) * 4;   // staging coords

    // ---------------- Phase 1: Wh ----------------
    float acc[2][4][4];
#pragma unroll
    for (int mt = 0; mt < 2; mt++)
#pragma unroll
        for (int nt = 0; nt < 4; nt++)
#pragma unroll
            for (int r = 0; r < 4; r++) acc[mt][nt][r] = 0.f;

    float4 pre[4];
    // load chunk 0, store -> buf0
#pragma unroll
    for (int i = 0; i < 4; i++) {
        int gr = bm + srow + i * 16;
        pre[i] = make_float4(0.f, 0.f, 0.f, 0.f);
        if (gr < N) pre[i] = *(const float4*)(x + (size_t)gr * INDIM + skq);
    }
#pragma unroll
    for (int i = 0; i < 4; i++) {
        int row = srow + i * 16;
        float4 v = pre[i];
        unsigned short hx, lx, hy, ly, hz, lz, hw, lw;
        split2(v.x, hx, lx); split2(v.y, hy, ly);
        split2(v.z, hz, lz); split2(v.w, hw, lw);
        *(uint2*)&A[0][0][row * ASTRIDE + skq] =
            make_uint2(((uint32_t)hy << 16) | hx, ((uint32_t)hw << 16) | hz);
        *(uint2*)&A[0][1][row * ASTRIDE + skq] =
            make_uint2(((uint32_t)ly << 16) | lx, ((uint32_t)lw << 16) | lz);
    }
    // prefetch chunk 1 into regs
#pragma unroll
    for (int i = 0; i < 4; i++) {
        int gr = bm + srow + i * 16;
        pre[i] = make_float4(0.f, 0.f, 0.f, 0.f);
        if (gr < N) pre[i] = *(const float4*)(x + (size_t)gr * INDIM + 64 + skq);
    }
    __syncthreads();

#pragma unroll
    for (int kc = 0; kc < 4; kc++) {
        int cur = kc & 1;
        // STS chunk kc+1 into the other buffer (data already in regs)
        if (kc < 3) {
#pragma unroll
            for (int i = 0; i < 4; i++) {
                int row = srow + i * 16;
                float4 v = pre[i];
                unsigned short hx, lx, hy, ly, hz, lz, hw, lw;
                split2(v.x, hx, lx); split2(v.y, hy, ly);
                split2(v.z, hz, lz); split2(v.w, hw, lw);
                *(uint2*)&A[cur ^ 1][0][row * ASTRIDE + skq] =
                    make_uint2(((uint32_t)hy << 16) | hx, ((uint32_t)hw << 16) | hz);
                *(uint2*)&A[cur ^ 1][1][row * ASTRIDE + skq] =
                    make_uint2(((uint32_t)ly << 16) | lx, ((uint32_t)lw << 16) | lz);
            }
            // LDG chunk kc+2 (latency hides behind the mma phase below)
            if (kc < 2) {
#pragma unroll
                for (int i = 0; i < 4; i++) {
                    int gr = bm + srow + i * 16;
                    pre[i] = make_float4(0.f, 0.f, 0.f, 0.f);
                    if (gr < N)
                        pre[i] = *(const float4*)(x + (size_t)gr * INDIM + (kc + 2) * 64 + skq);
                }
            }
        }
        // mma over chunk kc from buf[cur]
        uint32_t ah_b = su32(A[cur][0]), al_b = su32(A[cur][1]);
#pragma unroll
        for (int kk = 0; kk < 4; kk++) {
            uint32_t afh[2][4], afl[2][4];
#pragma unroll
            for (int mt = 0; mt < 2; mt++) {
                uint32_t off = ((wm * 32 + mt * 16 + lrow) * ASTRIDE + kk * 16 + lch) * 2;
                ldmA(afh[mt], ah_b + off);
                ldmA(afl[mt], al_b + off);
            }
            int kt = kc * 4 + kk;
            const uint32_t* Bp = g_WB + (size_t)(kt * 16 + wn * 4) * 64 + lane * 2;
#pragma unroll
            for (int nt = 0; nt < 4; nt++) {
                uint2 bh = *(const uint2*)(Bp + nt * 64);
                uint2 bl = *(const uint2*)(Bp + nt * 64 + 16384);
#pragma unroll
                for (int mt = 0; mt < 2; mt++) {
                    mma_bf16(acc[mt][nt], afh[mt], bh.x, bh.y);
                    mma_bf16(acc[mt][nt], afh[mt], bl.x, bl.y);
                    mma_bf16(acc[mt][nt], afl[mt], bh.x, bh.y);
                }
            }
        }
        __syncthreads();
    }

    // ---------------- Phase 2: epilogue + re-stage Wh (split) ----------------
    {
        int g = lane >> 2, cc = lane & 3;
#pragma unroll
        for (int mt = 0; mt < 2; mt++)
#pragma unroll
            for (int nt = 0; nt < 4; nt++) {
                int lrow0 = wm * 32 + mt * 16 + g;       // local tile row
                int col = wn * 32 + nt * 8 + cc * 2;
                int h = col >> 6, kl = col & 63;
                unsigned short h0, l0, h1, l1, h2, l2, h3, l3;
                split2(acc[mt][nt][0], h0, l0);
                split2(acc[mt][nt][1], h1, l1);
                split2(acc[mt][nt][2], h2, l2);
                split2(acc[mt][nt][3], h3, l3);
                *(uint32_t*)&A[h][0][lrow0 * ASTRIDE + kl] = ((uint32_t)h1 << 16) | h0;
                *(uint32_t*)&A[h][1][lrow0 * ASTRIDE + kl] = ((uint32_t)l1 << 16) | l0;
                *(uint32_t*)&A[h][0][(lrow0 + 8) * ASTRIDE + kl] = ((uint32_t)h3 << 16) | h2;
                *(uint32_t*)&A[h][1][(lrow0 + 8) * ASTRIDE + kl] = ((uint32_t)l3 << 16) | l2;
                int grow0 = bm + lrow0;
                if (grow0 < N)
                    *(float2*)(g_Wh + (size_t)grow0 * HDIM + col) =
                        make_float2(acc[mt][nt][0], acc[mt][nt][1]);
                if (grow0 + 8 < N)
                    *(float2*)(g_Wh + (size_t)(grow0 + 8) * HDIM + col) =
                        make_float2(acc[mt][nt][2], acc[mt][nt][3]);
            }
    }
    __syncthreads();

    // ---------------- Phase 3: U/V (wide R11 version) ----------------
    {
        int q = wid >> 1, nh = wid & 1, h = q & 1;
        uint32_t uah_b = su32(A[h][0]), ual_b = su32(A[h][1]);
        float uacc[4][4][4];
#pragma unroll
        for (int mt = 0; mt < 4; mt++)
#pragma unroll
            for (int nt = 0; nt < 4; nt++)
#pragma unroll
                for (int r = 0; r < 4; r++) uacc[mt][nt][r] = 0.f;

#pragma unroll
        for (int kk = 0; kk < 4; kk++) {
            uint32_t afh[4][4], afl[4][4];
#pragma unroll
            for (int mt = 0; mt < 4; mt++) {
                uint32_t off = ((mt * 16 + lrow) * ASTRIDE + kk * 16 + lch) * 2;
                ldmA(afh[mt], uah_b + off);
                ldmA(afl[mt], ual_b + off);
            }
            const uint32_t* Bp = g_WaB + (size_t)((q * 4 + kk) * 8 + nh * 4) * 64 + lane * 2;
#pragma unroll
            for (int nt = 0; nt < 4; nt++) {
                uint2 bh = *(const uint2*)(Bp + nt * 64);
                uint2 bl = *(const uint2*)(Bp + nt * 64 + 8192);
#pragma unroll
                for (int mt = 0; mt < 4; mt++) {
                    mma_bf16(uacc[mt][nt], afh[mt], bh.x, bh.y);
                    mma_bf16(uacc[mt][nt], afh[mt], bl.x, bl.y);
                    mma_bf16(uacc[mt][nt], afl[mt], bh.x, bh.y);
                }
            }
        }

        float* base = (q >> 1) ? g_V : g_U;
        int g = lane >> 2, cc = lane & 3;
#pragma unroll
        for (int mt = 0; mt < 4; mt++)
#pragma unroll
            for (int nt = 0; nt < 4; nt++) {
                int row0 = bm + mt * 16 + g;
                int col = h * 64 + nh * 32 + nt * 8 + cc * 2;
                if (row0 < N)
                    *(float2*)(base + (size_t)row0 * HDIM + col) =
                        make_float2(uacc[mt][nt][0], uacc[mt][nt][1]);
                if (row0 + 8 < N)
                    *(float2*)(base + (size_t)(row0 + 8) * HDIM + col) =
                        make_float2(uacc[mt][nt][2], uacc[mt][nt][3]);
            }
    }
}

// ---------------------------------------------------------------------------
// K3: fused edge kernel — single-pass online softmax + aggregation,
// 2 edges per iteration. One warp per dst node. (unchanged)
// ---------------------------------------------------------------------------
__global__ __launch_bounds__(256) void k_edge_fused(const float* __restrict__ avec,
                                                    const int* __restrict__ src,
                                                    float* __restrict__ out, int N) {
    int t = blockIdx.x * blockDim.x + threadIdx.x;
    int n = t >> 5, lane = t & 31;
    if (n >= N) return;
    int e0 = g_rowptr[n], e1 = g_rowptr[n + 1];
    const float4* U4  = (const float4*)g_U;
    const float4* V4  = (const float4*)g_V;
    const float4* Wh4 = (const float4*)g_Wh;
    float4 a = ((const float4*)avec)[lane];
    float4 acc = make_float4(0.f, 0.f, 0.f, 0.f);
    float ssum = 0.f;

    if (e1 > e0) {
        float4 v = V4[(size_t)n * 32 + lane];
        float m = -1e30f;

        float4 u0 = make_float4(0.f, 0.f, 0.f, 0.f), w0 = u0, u1 = u0, w1 = u0;
        {
            int s0 = src[e0];
            u0 = U4[(size_t)s0 * 32 + lane];
            w0 = Wh4[(size_t)s0 * 32 + lane];
            if (e0 + 1 < e1) {
                int s1 = src[e0 + 1];
                u1 = U4[(size_t)s1 * 32 + lane];
                w1 = Wh4[(size_t)s1 * 32 + lane];
            }
        }

        for (int e = e0; e < e1; e += 2) {
            bool two = (e + 1 < e1);
            float4 cu0 = u0, cw0 = w0, cu1 = u1, cw1 = w1;
            if (e + 2 < e1) {
                int s0 = src[e + 2];
                u0 = U4[(size_t)s0 * 32 + lane];
                w0 = Wh4[(size_t)s0 * 32 + lane];
            }
            if (e + 3 < e1) {
                int s1 = src[e + 3];
                u1 = U4[(size_t)s1 * 32 + lane];
                w1 = Wh4[(size_t)s1 * 32 + lane];
            }
            float q, z0, z1;
            q = cu0.x + v.x; z0  = fmaxf(q, ALPHA_C * q) * a.x;
            q = cu1.x + v.x; z1  = fmaxf(q, ALPHA_C * q) * a.x;
            q = cu0.y + v.y; z0 += fmaxf(q, ALPHA_C * q) * a.y;
            q = cu1.y + v.y; z1 += fmaxf(q, ALPHA_C * q) * a.y;
            q = cu0.z + v.z; z0 += fmaxf(q, ALPHA_C * q) * a.z;
            q = cu1.z + v.z; z1 += fmaxf(q, ALPHA_C * q) * a.z;
            q = cu0.w + v.w; z0 += fmaxf(q, ALPHA_C * q) * a.w;
            q = cu1.w + v.w; z1 += fmaxf(q, ALPHA_C * q) * a.w;
            z0 += __shfl_xor_sync(0xffffffffu, z0, 8);
            z1 += __shfl_xor_sync(0xffffffffu, z1, 8);
            z0 += __shfl_xor_sync(0xffffffffu, z0, 4);
            z1 += __shfl_xor_sync(0xffffffffu, z1, 4);
            z0 += __shfl_xor_sync(0xffffffffu, z0, 2);
            z1 += __shfl_xor_sync(0xffffffffu, z1, 2);
            z0 += __shfl_xor_sync(0xffffffffu, z0, 1);
            z1 += __shfl_xor_sync(0xffffffffu, z1, 1);
            float l0 = z0 * INV_TEMP;
            float l1 = two ? (z1 * INV_TEMP) : -1e30f;
            float mn = fmaxf(m, fmaxf(l0, l1));
            float cs = __expf(m - mn);
            float p0 = __expf(l0 - mn);
            float p1 = __expf(l1 - mn);
            ssum = ssum * cs + p0 + p1;
            acc.x = acc.x * cs + p0 * cw0.x + p1 * cw1.x;
            acc.y = acc.y * cs + p0 * cw0.y + p1 * cw1.y;
            acc.z = acc.z * cs + p0 * cw0.z + p1 * cw1.z;
            acc.w = acc.w * cs + p0 * cw0.w + p1 * cw1.w;
            m = mn;
        }
        float inv = 1.0f / (ssum + 1e-9f);
        acc.x *= inv; acc.y *= inv; acc.z *= inv; acc.w *= inv;
    }

    float bx = __shfl_down_sync(0xffffffffu, acc.x, 16);
    float by = __shfl_down_sync(0xffffffffu, acc.y, 16);
    float bz = __shfl_down_sync(0xffffffffu, acc.z, 16);
    float bw = __shfl_down_sync(0xffffffffu, acc.w, 16);
    if (lane < 16) {
        float4 r = make_float4((acc.x + bx) * 0.5f, (acc.y + by) * 0.5f,
                               (acc.z + bz) * 0.5f, (acc.w + bw) * 0.5f);
        ((float4*)out)[(size_t)n * 16 + lane] = r;
    }
}

// ---------------------------------------------------------------------------
extern "C" void kernel_launch(void* const* d_in, const int* in_sizes, int n_in,
                              void* d_out, int out_size) {
    const float* x     = (const float*)d_in[0];
    const float* W     = (const float*)d_in[1];
    const float* Wattn = (const float*)d_in[2];
    const float* avec  = (const float*)d_in[3];
    const int*   src   = (const int*)d_in[4];
    const int*   dst   = (const int*)d_in[5];
    float* out = (float*)d_out;
    int N = in_sizes[0] / INDIM;
    int E = in_sizes[4];

    k_rowptr<<<(E + 1 + 255) / 256, 256>>>(dst, E, N);
    k_prep_w<<<64, 256>>>(W);
    k_prep_wa<<<32, 256>>>(Wattn);
    k_whuv_mma<<<(N + 63) / 64, 256>>>(x, N);
    k_edge_fused<<<(N + 7) / 8, 256>>>(avec, src, out, N);
}